// round 6
// baseline (speedup 1.0000x reference)
#include <cuda_runtime.h>
#include <math_constants.h>

#define NROWS   131072
#define DDIM    64
#define KCODES  1024
#define KC      128
#define NCHUNK  8
#define NTHR    512
#define STR     132          // padded smem row stride (floats); 132*4 B keeps 16B alignment
#define SM_FLOATS (64*STR + 64*STR + KC + 128*STR)

// ---- packed f32x2 helpers (Blackwell) ----
#define FFMA2(acc, a, b) \
    asm("fma.rn.f32x2 %0, %1, %2, %0;" : "+l"(acc) : "l"(a), "l"(b))
#define PACK2(out, lo, hi) \
    asm("mov.b64 %0, {%1, %2};" : "=l"(out) : "r"(lo), "r"(hi))
#define UNPACK2(lo, hi, in) \
    asm("mov.b64 {%0, %1}, %2;" : "=r"(lo), "=r"(hi) : "l"(in))

__device__ __forceinline__ unsigned rotl32(unsigned x, int r) {
    return __funnelshift_l(x, x, r);
}

// threefry2x32, key (0,42) — jax.random.key(42), partitionable path:
// bits[j] = o0 ^ o1 with counter (0, j).
__device__ __forceinline__ unsigned threefry_xor_0_42(unsigned c1) {
    const unsigned ks0 = 0u;
    const unsigned ks1 = 42u;
    const unsigned ks2 = 0x1BD11BDAu ^ ks0 ^ ks1;
    unsigned x0 = 0u + ks0;
    unsigned x1 = c1 + ks1;
#define TFR(r) { x0 += x1; x1 = rotl32(x1, r); x1 ^= x0; }
    TFR(13) TFR(15) TFR(26) TFR(6)
    x0 += ks1; x1 += ks2 + 1u;
    TFR(17) TFR(29) TFR(16) TFR(24)
    x0 += ks2; x1 += ks0 + 2u;
    TFR(13) TFR(15) TFR(26) TFR(6)
    x0 += ks0; x1 += ks1 + 3u;
    TFR(17) TFR(29) TFR(16) TFR(24)
    x0 += ks1; x1 += ks2 + 4u;
    TFR(13) TFR(15) TFR(26) TFR(6)
    x0 += ks2; x1 += ks0 + 5u;
#undef TFR
    return x0 ^ x1;
}

// jax: u = max(tiny, (bits>>9)*2^-23);  g = -log(-log(u))
// log1pf branch keeps the winning-tail gumbels (u→1) accurate.
__device__ __forceinline__ float gumbel_from_bits(unsigned bits) {
    float u = (float)(bits >> 9) * 1.1920928955078125e-7f;
    u = fmaxf(u, 1.17549435e-38f);
    float v = (u < 0.5f) ? (-__logf(u)) : (-log1pf(u - 1.0f));
    return -__logf(v);
}

__global__ __launch_bounds__(NTHR, 1)
void fused_quantize(const float* __restrict__ x,
                    const float* __restrict__ cbg,
                    const float* __restrict__ temp,
                    float* __restrict__ out,
                    int out_size)
{
    extern __shared__ float sm[];
    float* xs = sm;                    // [64 dims][128 rows]  stride STR
    float* cb = sm + 64*STR;           // [64 dims][128 codes] stride STR
    float* cn = cb + 64*STR;           // [KC] ||c||^2 (later: row softmax sums)
    float* es = cn + KC;               // [128 rows][KC] exp values (later: reduce scratch)

    const int tid = threadIdx.x;
    const int tx  = tid & 15;          // A: code-group of 8 / B: dim group
    const int ty  = tid >> 4;          // 0..31 : row group of 4
    const int rbase = blockIdx.x * 128;

    const float invT = 1.0f / temp[0];

    // ---- load x tile transposed (coalesced) ----
    for (int i = tid; i < 128*64; i += NTHR) {
        int r = i >> 6;
        int d = i & 63;
        xs[d*STR + r] = x[(rbase + r)*DDIM + d];
    }

    // persistent per-thread state: 4 rows (ty*4 .. ty*4+3)
    float sum4[4], best4[4];
    int   bi4[4];
#pragma unroll
    for (int i = 0; i < 4; i++) {
        sum4[i] = 0.f; best4[i] = -CUDART_INF_F; bi4[i] = 0;
    }
    // phase-B accumulators packed over kv-pairs: lanes (kv even, kv odd)
    unsigned long long accP[4][4];
#pragma unroll
    for (int rr = 0; rr < 4; rr++)
#pragma unroll
        for (int dd = 0; dd < 4; dd++) accP[rr][dd] = 0ull;

    for (int c = 0; c < NCHUNK; c++) {
        const int kb = c * KC;
        __syncthreads();   // prev chunk's cb/es fully consumed (covers xs on c==0)

        // ---- load codebook chunk transposed ----
        for (int i = tid; i < KC*64; i += NTHR) {
            int j = i >> 6;
            int d = i & 63;
            cb[d*STR + j] = cbg[(kb + j)*DDIM + d];
        }
        __syncthreads();

        // ---- per-code squared norms ----
        if (tid < KC) {
            float s = 0.f;
#pragma unroll 8
            for (int d = 0; d < 64; d++) {
                float v = cb[d*STR + tid];
                s = fmaf(v, v, s);
            }
            cn[tid] = s;
        }
        __syncthreads();

        // ====== Phase A: packed dots (4 rows x 4 code-pairs) + gumbel + exp ======
        unsigned long long dtp[4][4];   // lanes: (code 2jp, code 2jp+1)
#pragma unroll
        for (int i = 0; i < 4; i++)
#pragma unroll
            for (int jp = 0; jp < 4; jp++) dtp[i][jp] = 0ull;

#pragma unroll 8
        for (int d = 0; d < 64; d++) {
            const float* xrow = &xs[d*STR];
            float4 xv4 = *(const float4*)(xrow + ty*4);
            const ulonglong2* c64 = (const ulonglong2*)(&cb[d*STR + tx*8]);
            ulonglong2 cA = c64[0];     // pairs (j0,j1),(j2,j3)
            ulonglong2 cB = c64[1];     // pairs (j4,j5),(j6,j7)
            float xv[4] = {xv4.x, xv4.y, xv4.z, xv4.w};
#pragma unroll
            for (int i = 0; i < 4; i++) {
                unsigned long long xd;
                unsigned xb = __float_as_uint(xv[i]);
                PACK2(xd, xb, xb);
                FFMA2(dtp[i][0], xd, cA.x);
                FFMA2(dtp[i][1], xd, cA.y);
                FFMA2(dtp[i][2], xd, cB.x);
                FFMA2(dtp[i][3], xd, cB.y);
            }
        }

#pragma unroll
        for (int i = 0; i < 4; i++) {
            const int rl = ty*4 + i;
            const unsigned base = (unsigned)(rbase + rl)*1024u + (unsigned)(kb + tx*8);
            float e8[8];
#pragma unroll
            for (int jp = 0; jp < 4; jp++) {
                unsigned u0, u1;
                UNPACK2(u0, u1, dtp[i][jp]);
                float d0 = __uint_as_float(u0);
                float d1 = __uint_as_float(u1);
                const int j0 = jp*2, j1 = jp*2 + 1;
                unsigned bits0 = threefry_xor_0_42(base + (unsigned)j0);
                unsigned bits1 = threefry_xor_0_42(base + (unsigned)j1);
                float s0 = fmaf(2.0f, d0, -cn[tx*8 + j0]);   // neg_dist + ||x||^2
                float s1 = fmaf(2.0f, d1, -cn[tx*8 + j1]);
                if (s0 > best4[i]) { best4[i] = s0; bi4[i] = kb + tx*8 + j0; }
                if (s1 > best4[i]) { best4[i] = s1; bi4[i] = kb + tx*8 + j1; }
                float e0 = __expf((s0 + gumbel_from_bits(bits0)) * invT);
                float e1 = __expf((s1 + gumbel_from_bits(bits1)) * invT);
                sum4[i] += e0; sum4[i] += e1;
                e8[j0] = e0; e8[j1] = e1;
            }
            float* ep = &es[rl*STR + tx*8];
            *(float4*)(ep)     = make_float4(e8[0], e8[1], e8[2], e8[3]);
            *(float4*)(ep + 4) = make_float4(e8[4], e8[5], e8[6], e8[7]);
        }
        __syncthreads();

        // ====== Phase B: accP += e * codebook, packed over kv-pairs ======
        // thread owns rows ty*4..ty*4+3, dims {tx, tx+16, tx+32, tx+48}
#pragma unroll 4
        for (int kv = 0; kv < KC; kv += 4) {
            ulonglong2 cv2[4];
#pragma unroll
            for (int dd = 0; dd < 4; dd++)
                cv2[dd] = *(const ulonglong2*)&cb[(tx + dd*16)*STR + kv];
#pragma unroll
            for (int rr = 0; rr < 4; rr++) {
                ulonglong2 ev2 = *(const ulonglong2*)&es[(ty*4 + rr)*STR + kv];
#pragma unroll
                for (int dd = 0; dd < 4; dd++) {
                    FFMA2(accP[rr][dd], ev2.x, cv2[dd].x);
                    FFMA2(accP[rr][dd], ev2.y, cv2[dd].y);
                }
            }
        }
    }
    __syncthreads();

    // ---- cross-thread reductions over the 16 tx partials per row ----
    float* sred  = es;                  // [16][128]
    float* bredf = es + 16*128;         // [16][128]
    int*   bredi = (int*)(es + 32*128); // [16][128]
#pragma unroll
    for (int i = 0; i < 4; i++) {
        int rl = ty*4 + i;
        sred [tx*128 + rl] = sum4[i];
        bredf[tx*128 + rl] = best4[i];
        bredi[tx*128 + rl] = bi4[i];
    }
    __syncthreads();
    if (tid < 128) {
        int r = tid;
        float s = 0.f;
        float b = -CUDART_INF_F;
        int bi = 0;
#pragma unroll
        for (int t = 0; t < 16; t++) {
            s += sred[t*128 + r];
            float bv = bredf[t*128 + r];
            int   ii = bredi[t*128 + r];
            if (bv > b || (bv == b && ii < bi)) { b = bv; bi = ii; }
        }
        cn[r] = s;
        if (out_size >= NROWS*DDIM + NROWS)
            out[NROWS*DDIM + (rbase + r)] = (float)bi;
    }
    __syncthreads();

    // ---- write emb = (lo+hi of packed acc) / sum ----
#pragma unroll
    for (int rr = 0; rr < 4; rr++) {
        int r = ty*4 + rr;
        float inv = 1.0f / cn[r];
#pragma unroll
        for (int dd = 0; dd < 4; dd++) {
            unsigned lo, hi;
            UNPACK2(lo, hi, accP[rr][dd]);
            float a = __uint_as_float(lo) + __uint_as_float(hi);
            out[(rbase + r)*DDIM + tx + dd*16] = a * inv;
        }
    }
}

extern "C" void kernel_launch(void* const* d_in, const int* in_sizes, int n_in,
                              void* d_out, int out_size) {
    const float* x  = (const float*)d_in[0];
    const float* cb = (const float*)d_in[1];
    const float* t  = (const float*)d_in[2];
    float* out = (float*)d_out;

    size_t smem = SM_FLOATS * sizeof(float);   // 135680 B
    cudaFuncSetAttribute(fused_quantize,
                         cudaFuncAttributeMaxDynamicSharedMemorySize, (int)smem);
    fused_quantize<<<NROWS/128, NTHR, smem>>>(x, cb, t, out, out_size);
}

// round 8
// speedup vs baseline: 1.2071x; 1.2071x over previous
#include <cuda_runtime.h>
#include <cuda_bf16.h>
#include <math_constants.h>
#include <cstdint>

#define NROWS   131072
#define DDIM    64
#define KCODES  1024
#define KC      128
#define NCHUNK  8
#define NTHR    512
#define STR     132          // fp32 smem stride (dim-major tiles)
#define ESTRB   272          // E bf16 tile row stride in BYTES (136 elems)
#define CSTRB   144          // C bf16 tile row stride in BYTES (72 elems)

// ---- smem byte layout ----
#define OFF_XS   0                            // 64*STR*4   = 33792
#define OFF_CB   33792                        // 64*STR*4   = 33792
#define OFF_CN   67584                        // 128*4      = 512
#define OFF_EHI  68096                        // 128*ESTRB  = 34816
#define OFF_ELO  102912                       // 34816
#define OFF_CHI  137728                       // 128*CSTRB  = 18432
#define OFF_CLO  156160                       // 18432
#define SMEM_TOTAL 174592

__device__ __forceinline__ uint32_t smem_u32(const void* p) {
    uint32_t a;
    asm("{ .reg .u64 t; cvta.to.shared.u64 t, %1; cvt.u32.u64 %0, t; }" : "=r"(a) : "l"(p));
    return a;
}

#define LDSM_X4(r0,r1,r2,r3, addr) \
    asm volatile("ldmatrix.sync.aligned.m8n8.x4.shared.b16 {%0,%1,%2,%3}, [%4];" \
                 : "=r"(r0),"=r"(r1),"=r"(r2),"=r"(r3) : "r"(addr))
#define LDSM_X2T(r0,r1, addr) \
    asm volatile("ldmatrix.sync.aligned.m8n8.x2.trans.shared.b16 {%0,%1}, [%2];" \
                 : "=r"(r0),"=r"(r1) : "r"(addr))
#define MMA16816(d, a0,a1,a2,a3, b0,b1) \
    asm volatile("mma.sync.aligned.m16n8k16.row.col.f32.bf16.bf16.f32 " \
                 "{%0,%1,%2,%3}, {%4,%5,%6,%7}, {%8,%9}, {%0,%1,%2,%3};" \
                 : "+f"(d[0]),"+f"(d[1]),"+f"(d[2]),"+f"(d[3]) \
                 : "r"(a0),"r"(a1),"r"(a2),"r"(a3), "r"(b0),"r"(b1))

__device__ __forceinline__ unsigned rotl32(unsigned x, int r) {
    return __funnelshift_l(x, x, r);
}

// threefry2x32, key (0,42) — jax partitionable path: bits[j] = o0^o1, counter (0,j)
__device__ __forceinline__ unsigned threefry_xor_0_42(unsigned c1) {
    const unsigned ks0 = 0u, ks1 = 42u;
    const unsigned ks2 = 0x1BD11BDAu ^ ks0 ^ ks1;
    unsigned x0 = 0u + ks0;
    unsigned x1 = c1 + ks1;
#define TFR(r) { x0 += x1; x1 = rotl32(x1, r); x1 ^= x0; }
    TFR(13) TFR(15) TFR(26) TFR(6)
    x0 += ks1; x1 += ks2 + 1u;
    TFR(17) TFR(29) TFR(16) TFR(24)
    x0 += ks2; x1 += ks0 + 2u;
    TFR(13) TFR(15) TFR(26) TFR(6)
    x0 += ks0; x1 += ks1 + 3u;
    TFR(17) TFR(29) TFR(16) TFR(24)
    x0 += ks1; x1 += ks2 + 4u;
    TFR(13) TFR(15) TFR(26) TFR(6)
    x0 += ks2; x1 += ks0 + 5u;
#undef TFR
    return x0 ^ x1;
}

__device__ __forceinline__ float gumbel_from_bits(unsigned bits) {
    float u = (float)(bits >> 9) * 1.1920928955078125e-7f;
    u = fmaxf(u, 1.17549435e-38f);
    float v = (u < 0.5f) ? (-__logf(u)) : (-log1pf(u - 1.0f));
    return -__logf(v);
}

__device__ __forceinline__ uint32_t pack_hi2(float a, float b,
                                             float& ra, float& rb) {
    __nv_bfloat16 ha = __float2bfloat16(a);
    __nv_bfloat16 hb = __float2bfloat16(b);
    ra = a - __bfloat162float(ha);
    rb = b - __bfloat162float(hb);
    return (uint32_t)__bfloat16_as_ushort(ha) | ((uint32_t)__bfloat16_as_ushort(hb) << 16);
}
__device__ __forceinline__ uint32_t pack_bf2(float a, float b) {
    __nv_bfloat16 ha = __float2bfloat16(a);
    __nv_bfloat16 hb = __float2bfloat16(b);
    return (uint32_t)__bfloat16_as_ushort(ha) | ((uint32_t)__bfloat16_as_ushort(hb) << 16);
}

__global__ __launch_bounds__(NTHR, 1)
void fused_quantize(const float* __restrict__ x,
                    const float* __restrict__ cbg,
                    const float* __restrict__ temp,
                    float* __restrict__ out,
                    int out_size)
{
    extern __shared__ char smem[];
    const uint32_t sb = smem_u32(smem);
    float* xs = (float*)(smem + OFF_XS);
    float* cb = (float*)(smem + OFF_CB);
    float* cn = (float*)(smem + OFF_CN);

    const int tid = threadIdx.x;
    const int wid = tid >> 5;
    const int lane = tid & 31;
    const int tx  = tid & 15;
    const int ty  = tid >> 4;
    const int rbase = blockIdx.x * 128;

    const float invT = 1.0f / temp[0];

    // phase-B warp tile: rows r0..r0+15, dims c0base..+31
    const int wr = wid & 7;
    const int wc = wid >> 3;
    const int r0 = wr * 16;
    // ldmatrix A lane address components
    const int a_row  = r0 + (lane & 7) + ((lane >> 3) & 1) * 8;
    const int a_colB = (((lane >> 4) & 1) * 8) * 2;          // byte offset of k-subtile
    const uint32_t aoff = (uint32_t)(a_row * ESTRB + a_colB);
    const int b_row = lane & 15;

    // ---- load x tile transposed (dim-major, coalesced) ----
    for (int i = tid; i < 128*64; i += NTHR) {
        int r = i >> 6;
        int d = i & 63;
        xs[d*STR + r] = x[(rbase + r)*DDIM + d];
    }

    float sum4[4], best4[4];
    int   bi4[4];
#pragma unroll
    for (int i = 0; i < 4; i++) {
        sum4[i] = 0.f; best4[i] = -CUDART_INF_F; bi4[i] = 0;
    }
    float acc[4][4];
#pragma unroll
    for (int nt = 0; nt < 4; nt++)
#pragma unroll
        for (int q = 0; q < 4; q++) acc[nt][q] = 0.f;

    for (int c = 0; c < NCHUNK; c++) {
        const int kb = c * KC;
        __syncthreads();   // prev chunk's E/C tiles fully consumed by mma; cb free

        // ---- load codebook chunk fp32 transposed (dim-major) ----
        for (int i = tid; i < KC*64; i += NTHR) {
            int j = i >> 6;
            int d = i & 63;
            cb[d*STR + j] = cbg[(kb + j)*DDIM + d];
        }
        // ---- build C bf16 hi/lo tiles [code][dim] from gmem (L2-hot) ----
        {
            const float4* cbg4 = (const float4*)cbg;
#pragma unroll
            for (int i = 0; i < 4; i++) {
                int q = tid + i*NTHR;               // float4 index within chunk
                int code = q >> 4;
                int dim4 = (q & 15) * 4;
                float4 v = cbg4[kb*16 + q];
                float l0, l1, l2, l3;
                uint32_t h01 = pack_hi2(v.x, v.y, l0, l1);
                uint32_t h23 = pack_hi2(v.z, v.w, l2, l3);
                uint32_t base = (uint32_t)(code*CSTRB + dim4*2);
                *(uint2*)(smem + OFF_CHI + base) = make_uint2(h01, h23);
                *(uint2*)(smem + OFF_CLO + base) = make_uint2(pack_bf2(l0, l1), pack_bf2(l2, l3));
            }
        }
        __syncthreads();   // cb + C tiles visible

        // ---- per-code squared norms ----
        if (tid < KC) {
            float s = 0.f;
#pragma unroll 8
            for (int d = 0; d < 64; d++) {
                float v = cb[d*STR + tid];
                s = fmaf(v, v, s);
            }
            cn[tid] = s;
        }
        __syncthreads();

        // ================= Phase A: fp32 dots (4 rows x 8 codes) =================
        float dt[4][8];
#pragma unroll
        for (int i = 0; i < 4; i++)
#pragma unroll
            for (int j = 0; j < 8; j++) dt[i][j] = 0.f;

#pragma unroll 8
        for (int d = 0; d < 64; d++) {
            const float* xrow = &xs[d*STR];
            float4 xv4 = *(const float4*)(xrow + ty*4);
            const float* crow = &cb[d*STR + tx*8];
            float4 c0 = *(const float4*)(crow);
            float4 c1 = *(const float4*)(crow + 4);
            float xv[4] = {xv4.x, xv4.y, xv4.z, xv4.w};
            float cv[8] = {c0.x, c0.y, c0.z, c0.w, c1.x, c1.y, c1.z, c1.w};
#pragma unroll
            for (int i = 0; i < 4; i++)
#pragma unroll
                for (int j = 0; j < 8; j++)
                    dt[i][j] = fmaf(xv[i], cv[j], dt[i][j]);
        }

        // hoist code norms for this thread's 8 codes
        float cnr[8];
#pragma unroll
        for (int j = 0; j < 8; j++) cnr[j] = cn[tx*8 + j];

        // ---- epilogue: argmax, gumbel, exp, bf16 split into E tiles ----
#pragma unroll
        for (int i = 0; i < 4; i++) {
            const int rl = ty*4 + i;
            const unsigned base = (unsigned)(rbase + rl)*1024u + (unsigned)(kb + tx*8);
            float e8[8];
#pragma unroll
            for (int j = 0; j < 8; j++) {
                unsigned bits = threefry_xor_0_42(base + (unsigned)j);
                float s = fmaf(2.0f, dt[i][j], -cnr[j]);
                if (s > best4[i]) { best4[i] = s; bi4[i] = kb + tx*8 + j; }
                float e = __expf((s + gumbel_from_bits(bits)) * invT);
                sum4[i] += e;
                e8[j] = e;
            }
            float l0,l1,l2,l3,l4,l5,l6,l7;
            uint32_t h0 = pack_hi2(e8[0], e8[1], l0, l1);
            uint32_t h1 = pack_hi2(e8[2], e8[3], l2, l3);
            uint32_t h2 = pack_hi2(e8[4], e8[5], l4, l5);
            uint32_t h3 = pack_hi2(e8[6], e8[7], l6, l7);
            uint32_t boff = (uint32_t)(rl*ESTRB + tx*16);
            *(uint4*)(smem + OFF_EHI + boff) = make_uint4(h0, h1, h2, h3);
            *(uint4*)(smem + OFF_ELO + boff) =
                make_uint4(pack_bf2(l0,l1), pack_bf2(l2,l3), pack_bf2(l4,l5), pack_bf2(l6,l7));
        }
        __syncthreads();   // E tiles visible to all warps

        // ========== Phase B: tensor-core  acc += E(128xKC) * C(KCx64) ==========
#pragma unroll
        for (int ks = 0; ks < 8; ks++) {
            const int k0 = ks * 16;
            uint32_t ah0,ah1,ah2,ah3, al0,al1,al2,al3;
            LDSM_X4(ah0,ah1,ah2,ah3, sb + OFF_EHI + aoff + k0*2);
            LDSM_X4(al0,al1,al2,al3, sb + OFF_ELO + aoff + k0*2);
            uint32_t browoff = (uint32_t)((k0 + b_row) * CSTRB);
#pragma unroll
            for (int nt = 0; nt < 4; nt++) {
                uint32_t n2 = (uint32_t)((wc*32 + nt*8) * 2);
                uint32_t bh0, bh1, bl0, bl1;
                LDSM_X2T(bh0, bh1, sb + OFF_CHI + browoff + n2);
                LDSM_X2T(bl0, bl1, sb + OFF_CLO + browoff + n2);
                MMA16816(acc[nt], ah0,ah1,ah2,ah3, bh0,bh1);
                MMA16816(acc[nt], ah0,ah1,ah2,ah3, bl0,bl1);
                MMA16816(acc[nt], al0,al1,al2,al3, bh0,bh1);
            }
        }
    }
    __syncthreads();   // all mma reads done; E region reusable as scratch

    // ---- cross-thread reductions over the 16 tx partials per row ----
    float* sred  = (float*)(smem + OFF_EHI);       // [16][128]
    float* bredf = sred + 16*128;                  // [16][128]
    int*   bredi = (int*)(bredf + 16*128);         // [16][128]
#pragma unroll
    for (int i = 0; i < 4; i++) {
        int rl = ty*4 + i;
        sred [tx*128 + rl] = sum4[i];
        bredf[tx*128 + rl] = best4[i];
        bredi[tx*128 + rl] = bi4[i];
    }
    __syncthreads();
    if (tid < 128) {
        int r = tid;
        float s = 0.f;
        float b = -CUDART_INF_F;
        int bi = 0;
#pragma unroll
        for (int t = 0; t < 16; t++) {
            s += sred[t*128 + r];
            float bv = bredf[t*128 + r];
            int   ii = bredi[t*128 + r];
            if (bv > b || (bv == b && ii < bi)) { b = bv; bi = ii; }
        }
        cn[r] = s;
        if (out_size >= NROWS*DDIM + NROWS)
            out[NROWS*DDIM + (rbase + r)] = (float)bi;
    }
    __syncthreads();

    // ---- write emb = acc / sum from mma accumulators ----
    {
        const int row_a = r0 + (lane >> 2);
        const int row_b = row_a + 8;
        const float inva = 1.0f / cn[row_a];
        const float invb = 1.0f / cn[row_b];
        float* oa = out + (size_t)(rbase + row_a)*DDIM;
        float* ob = out + (size_t)(rbase + row_b)*DDIM;
#pragma unroll
        for (int nt = 0; nt < 4; nt++) {
            int col = wc*32 + nt*8 + (lane & 3)*2;
            *(float2*)(oa + col) = make_float2(acc[nt][0]*inva, acc[nt][1]*inva);
            *(float2*)(ob + col) = make_float2(acc[nt][2]*invb, acc[nt][3]*invb);
        }
    }
}

extern "C" void kernel_launch(void* const* d_in, const int* in_sizes, int n_in,
                              void* d_out, int out_size) {
    const float* x  = (const float*)d_in[0];
    const float* cb = (const float*)d_in[1];
    const float* t  = (const float*)d_in[2];
    float* out = (float*)d_out;

    cudaFuncSetAttribute(fused_quantize,
                         cudaFuncAttributeMaxDynamicSharedMemorySize, SMEM_TOTAL);
    fused_quantize<<<NROWS/128, NTHR, SMEM_TOTAL>>>(x, cb, t, out, out_size);
}

// round 11
// speedup vs baseline: 1.3760x; 1.1399x over previous
#include <cuda_runtime.h>
#include <cuda_bf16.h>
#include <math_constants.h>
#include <cstdint>

#define NROWS   131072
#define DDIM    64
#define KCODES  1024
#define KC      128
#define NCHUNK  8
#define NTHR    512
#define XSTRB   144      // X bf16 tile row stride (bytes)
#define CTSTRB  272      // Ct (dim-major) tile row stride
#define CSTRB   144      // C  (code-major) tile row stride
#define ESTRB   272      // E  tile row stride
#define GAP_T   4e-3f

// ---- smem byte layout ----
#define OFF_XH    0                  // 128*144 = 18432
#define OFF_XL    18432
#define OFF_CTH   36864              // 64*272 = 17408
#define OFF_CTL   54272
#define OFF_CH    71680              // 128*144 = 18432
#define OFF_CL    90112
#define OFF_EH    108544             // 128*272 = 34816 (reused: reduction scratch)
#define OFF_EL    143360
#define OFF_CN    178176             // 128*4 (norms, later row sums)
#define OFF_FLAGN 178688
#define OFF_FLAGL 178692             // up to 128 ints
#define SMEM_TOTAL 179456

__device__ __forceinline__ uint32_t smem_u32(const void* p) {
    uint32_t a;
    asm("{ .reg .u64 t; cvta.to.shared.u64 t, %1; cvt.u32.u64 %0, t; }" : "=r"(a) : "l"(p));
    return a;
}

#define LDSM_X4(r0,r1,r2,r3, addr) \
    asm volatile("ldmatrix.sync.aligned.m8n8.x4.shared.b16 {%0,%1,%2,%3}, [%4];" \
                 : "=r"(r0),"=r"(r1),"=r"(r2),"=r"(r3) : "r"(addr))
#define LDSM_X2T(r0,r1, addr) \
    asm volatile("ldmatrix.sync.aligned.m8n8.x2.trans.shared.b16 {%0,%1}, [%2];" \
                 : "=r"(r0),"=r"(r1) : "r"(addr))
#define MMA16816(d, a0,a1,a2,a3, b0,b1) \
    asm volatile("mma.sync.aligned.m16n8k16.row.col.f32.bf16.bf16.f32 " \
                 "{%0,%1,%2,%3}, {%4,%5,%6,%7}, {%8,%9}, {%0,%1,%2,%3};" \
                 : "+f"(d[0]),"+f"(d[1]),"+f"(d[2]),"+f"(d[3]) \
                 : "r"(a0),"r"(a1),"r"(a2),"r"(a3), "r"(b0),"r"(b1))

__device__ __forceinline__ unsigned rotl32(unsigned x, int r) {
    return __funnelshift_l(x, x, r);
}

// threefry2x32, key (0,42) — jax partitionable path: bits[j] = o0^o1, counter (0,j)
__device__ __forceinline__ unsigned threefry_xor_0_42(unsigned c1) {
    const unsigned ks0 = 0u, ks1 = 42u;
    const unsigned ks2 = 0x1BD11BDAu ^ ks0 ^ ks1;
    unsigned x0 = 0u + ks0;
    unsigned x1 = c1 + ks1;
#define TFR(r) { x0 += x1; x1 = rotl32(x1, r); x1 ^= x0; }
    TFR(13) TFR(15) TFR(26) TFR(6)
    x0 += ks1; x1 += ks2 + 1u;
    TFR(17) TFR(29) TFR(16) TFR(24)
    x0 += ks2; x1 += ks0 + 2u;
    TFR(13) TFR(15) TFR(26) TFR(6)
    x0 += ks0; x1 += ks1 + 3u;
    TFR(17) TFR(29) TFR(16) TFR(24)
    x0 += ks1; x1 += ks2 + 4u;
    TFR(13) TFR(15) TFR(26) TFR(6)
    x0 += ks2; x1 += ks0 + 5u;
#undef TFR
    return x0 ^ x1;
}

__device__ __forceinline__ float gumbel_from_bits(unsigned bits) {
    float u = (float)(bits >> 9) * 1.1920928955078125e-7f;
    u = fmaxf(u, 1.17549435e-38f);
    float v = (u < 0.5f) ? (-__logf(u)) : (-log1pf(u - 1.0f));
    return -__logf(v);
}

__device__ __forceinline__ void split_bf16(float v, unsigned short& h, unsigned short& l) {
    __nv_bfloat16 hb = __float2bfloat16(v);
    h = __bfloat16_as_ushort(hb);
    l = __bfloat16_as_ushort(__float2bfloat16(v - __bfloat162float(hb)));
}

__global__ __launch_bounds__(NTHR, 1)
void fused_quantize(const float* __restrict__ x,
                    const float* __restrict__ cbg,
                    const float* __restrict__ temp,
                    float* __restrict__ out,
                    int out_size)
{
    extern __shared__ char smem[];
    const uint32_t sb = smem_u32(smem);
    float* cnf = (float*)(smem + OFF_CN);

    const int tid  = threadIdx.x;
    const int wid  = tid >> 5;
    const int lane = tid & 31;
    const int wr   = wid & 7;          // row group (16 rows)
    const int wc   = wid >> 3;         // col half
    const int rbase = blockIdx.x * 128;
    const float invT = 1.0f / temp[0];
    const bool has_ids = (out_size >= NROWS*DDIM + NROWS);

    if (tid == 0) *(int*)(smem + OFF_FLAGN) = 0;

    // ldmatrix lane addressing (shared by phase A and B A-operands)
    const int a_row = wr*16 + (lane & 7) + ((lane >> 3) & 1)*8;
    const int a_col = ((lane >> 4) & 1) * 16;
    const uint32_t aoffX = (uint32_t)(a_row*XSTRB + a_col);
    const uint32_t aoffE = (uint32_t)(a_row*ESTRB + a_col);
    const int b_row = lane & 15;
    const int rowA  = wr*16 + (lane >> 2);

    // ---- build X bf16 hi/lo tiles [row][dim] (once; coalesced) ----
#pragma unroll
    for (int i = 0; i < 4; i++) {
        int q = tid + i*NTHR;          // 2048 float4s
        int row = q >> 4;
        int d4  = (q & 15) * 4;
        float4 v = *(const float4*)(x + (size_t)(rbase + row)*DDIM + d4);
        unsigned short h0,h1,h2,h3,l0,l1,l2,l3;
        split_bf16(v.x,h0,l0); split_bf16(v.y,h1,l1);
        split_bf16(v.z,h2,l2); split_bf16(v.w,h3,l3);
        uint32_t base = (uint32_t)(row*XSTRB + d4*2);
        *(uint2*)(smem + OFF_XH + base) =
            make_uint2((uint32_t)h0 | ((uint32_t)h1<<16), (uint32_t)h2 | ((uint32_t)h3<<16));
        *(uint2*)(smem + OFF_XL + base) =
            make_uint2((uint32_t)l0 | ((uint32_t)l1<<16), (uint32_t)l2 | ((uint32_t)l3<<16));
    }

    // persistent per-lane state: 2 rows (rowA, rowA+8)
    float sum2[2] = {0.f, 0.f};
    float pb1[2] = {-CUDART_INF_F, -CUDART_INF_F};
    float pb2[2] = {-CUDART_INF_F, -CUDART_INF_F};
    int   pi1[2] = {0, 0};
    float bacc[4][4];
#pragma unroll
    for (int nt = 0; nt < 4; nt++)
#pragma unroll
        for (int q = 0; q < 4; q++) bacc[nt][q] = 0.f;

    for (int c = 0; c < NCHUNK; c++) {
        const int kb = c * KC;
        __syncthreads();   // prev chunk's C/Ct/E consumed

        // ---- build C [code][dim] and Ct [dim][code] bf16 hi/lo tiles ----
        {
            const int code = tid & 127;
            const int dg   = tid >> 7;     // 16-dim group
            const float* src = cbg + (size_t)(kb + code)*DDIM + dg*16;
            unsigned short hs[16], ls[16];
#pragma unroll
            for (int i = 0; i < 4; i++) {
                float4 v = ((const float4*)src)[i];
                split_bf16(v.x, hs[i*4+0], ls[i*4+0]);
                split_bf16(v.y, hs[i*4+1], ls[i*4+1]);
                split_bf16(v.z, hs[i*4+2], ls[i*4+2]);
                split_bf16(v.w, hs[i*4+3], ls[i*4+3]);
            }
            uint32_t hp[8], lp[8];
#pragma unroll
            for (int i = 0; i < 8; i++) {
                hp[i] = (uint32_t)hs[2*i] | ((uint32_t)hs[2*i+1] << 16);
                lp[i] = (uint32_t)ls[2*i] | ((uint32_t)ls[2*i+1] << 16);
            }
            uint32_t cbase = (uint32_t)(code*CSTRB + dg*32);
            *(uint4*)(smem + OFF_CH + cbase)      = make_uint4(hp[0],hp[1],hp[2],hp[3]);
            *(uint4*)(smem + OFF_CH + cbase + 16) = make_uint4(hp[4],hp[5],hp[6],hp[7]);
            *(uint4*)(smem + OFF_CL + cbase)      = make_uint4(lp[0],lp[1],lp[2],lp[3]);
            *(uint4*)(smem + OFF_CL + cbase + 16) = make_uint4(lp[4],lp[5],lp[6],lp[7]);
#pragma unroll
            for (int t = 0; t < 16; t++) {
                int d = dg*16 + t;
                *(unsigned short*)(smem + OFF_CTH + d*CTSTRB + code*2) = hs[t];
                *(unsigned short*)(smem + OFF_CTL + d*CTSTRB + code*2) = ls[t];
            }
        }
        // ---- exact fp32 code norms from gmem ----
        if (tid < KC) {
            const float* src = cbg + (size_t)(kb + tid)*DDIM;
            float s = 0.f;
#pragma unroll
            for (int i = 0; i < 16; i++) {
                float4 v = ((const float4*)src)[i];
                s = fmaf(v.x, v.x, s); s = fmaf(v.y, v.y, s);
                s = fmaf(v.z, v.z, s); s = fmaf(v.w, v.w, s);
            }
            cnf[tid] = s;
        }
        __syncthreads();

        // ========== Phase A (tensor): S = X(128x64) * Ct(64x128), 3-split ==========
        float sacc[8][4];
#pragma unroll
        for (int nt = 0; nt < 8; nt++)
#pragma unroll
            for (int q = 0; q < 4; q++) sacc[nt][q] = 0.f;

#pragma unroll
        for (int ks = 0; ks < 4; ks++) {
            const int k0b = ks * 32;          // 16 dims * 2 bytes
            uint32_t ah0,ah1,ah2,ah3, al0,al1,al2,al3;
            LDSM_X4(ah0,ah1,ah2,ah3, sb + OFF_XH + aoffX + k0b);
            LDSM_X4(al0,al1,al2,al3, sb + OFF_XL + aoffX + k0b);
            uint32_t browoff = (uint32_t)((ks*16 + b_row) * CTSTRB);
#pragma unroll
            for (int nt = 0; nt < 8; nt++) {
                uint32_t n2 = (uint32_t)((wc*64 + nt*8) * 2);
                uint32_t bh0, bh1, bl0, bl1;
                LDSM_X2T(bh0, bh1, sb + OFF_CTH + browoff + n2);
                LDSM_X2T(bl0, bl1, sb + OFF_CTL + browoff + n2);
                MMA16816(sacc[nt], ah0,ah1,ah2,ah3, bh0,bh1);
                MMA16816(sacc[nt], ah0,ah1,ah2,ah3, bl0,bl1);
                MMA16816(sacc[nt], al0,al1,al2,al3, bh0,bh1);
            }
        }

        // hoist code norms for this lane's 16 codes
        float2 cnv[8];
#pragma unroll
        for (int nt = 0; nt < 8; nt++)
            cnv[nt] = *(float2*)(smem + OFF_CN + (wc*64 + nt*8 + (lane&3)*2)*4);

        // ---- epilogue on fragments: top2, gumbel, exp, E-tile write ----
#pragma unroll
        for (int slot = 0; slot < 2; slot++) {
            const int row = rowA + slot*8;
            const unsigned fb = (unsigned)(rbase + row)*1024u + (unsigned)kb;
            const uint32_t ebase = (uint32_t)(row*ESTRB + wc*128 + (lane&3)*4);
#pragma unroll
            for (int nt = 0; nt < 8; nt++) {
                const int c0 = wc*64 + nt*8 + (lane&3)*2;
                float s0 = fmaf(2.0f, sacc[nt][slot*2+0], -cnv[nt].x);
                float s1 = fmaf(2.0f, sacc[nt][slot*2+1], -cnv[nt].y);
                if (s0 > pb1[slot]) { pb2[slot] = pb1[slot]; pb1[slot] = s0; pi1[slot] = kb + c0; }
                else if (s0 > pb2[slot]) pb2[slot] = s0;
                if (s1 > pb1[slot]) { pb2[slot] = pb1[slot]; pb1[slot] = s1; pi1[slot] = kb + c0 + 1; }
                else if (s1 > pb2[slot]) pb2[slot] = s1;
                unsigned bt0 = threefry_xor_0_42(fb + (unsigned)c0);
                unsigned bt1 = threefry_xor_0_42(fb + (unsigned)c0 + 1u);
                float e0 = __expf((s0 + gumbel_from_bits(bt0)) * invT);
                float e1 = __expf((s1 + gumbel_from_bits(bt1)) * invT);
                sum2[slot] += e0 + e1;
                unsigned short h0,h1,l0,l1;
                split_bf16(e0,h0,l0); split_bf16(e1,h1,l1);
                *(uint32_t*)(smem + OFF_EH + ebase + nt*16) = (uint32_t)h0 | ((uint32_t)h1<<16);
                *(uint32_t*)(smem + OFF_EL + ebase + nt*16) = (uint32_t)l0 | ((uint32_t)l1<<16);
            }
        }
        __syncthreads();   // E visible

        // ========== Phase B (tensor): emb_raw += E(128x128) * C(128x64) ==========
#pragma unroll
        for (int ks = 0; ks < 8; ks++) {
            const int k0 = ks * 16;
            uint32_t ah0,ah1,ah2,ah3, al0,al1,al2,al3;
            LDSM_X4(ah0,ah1,ah2,ah3, sb + OFF_EH + aoffE + k0*2);
            LDSM_X4(al0,al1,al2,al3, sb + OFF_EL + aoffE + k0*2);
            uint32_t browoff = (uint32_t)((k0 + b_row) * CSTRB);
#pragma unroll
            for (int nt = 0; nt < 4; nt++) {
                uint32_t n2 = (uint32_t)((wc*32 + nt*8) * 2);
                uint32_t bh0, bh1, bl0, bl1;
                LDSM_X2T(bh0, bh1, sb + OFF_CH + browoff + n2);
                LDSM_X2T(bl0, bl1, sb + OFF_CL + browoff + n2);
                MMA16816(bacc[nt], ah0,ah1,ah2,ah3, bh0,bh1);
                MMA16816(bacc[nt], ah0,ah1,ah2,ah3, bl0,bl1);
                MMA16816(bacc[nt], al0,al1,al2,al3, bh0,bh1);
            }
        }
    }
    __syncthreads();   // all tiles consumed; EH reusable as scratch

    // ---- per-row reduction: 8 partials (4 quad-lanes x 2 wc) ----
    float* rsum = (float*)(smem + OFF_EH);
    float* rb1  = rsum + 8*128;
    float* rb2  = rb1  + 8*128;
    int*   ri1  = (int*)(rb2 + 8*128);
    const int p = wc*4 + (lane & 3);
#pragma unroll
    for (int slot = 0; slot < 2; slot++) {
        int row = rowA + slot*8;
        rsum[p*128 + row] = sum2[slot];
        rb1 [p*128 + row] = pb1[slot];
        rb2 [p*128 + row] = pb2[slot];
        ri1 [p*128 + row] = pi1[slot];
    }
    __syncthreads();
    if (tid < 128) {
        const int r = tid;
        float s = 0.f, b = -CUDART_INF_F, b2 = -CUDART_INF_F;
        int bi = 0;
#pragma unroll
        for (int t = 0; t < 8; t++) {
            s += rsum[t*128 + r];
            float v1 = rb1[t*128 + r];
            float v2 = rb2[t*128 + r];
            int   ii = ri1[t*128 + r];
            if (v1 > b || (v1 == b && ii < bi)) {
                b2 = fmaxf(b, v2);
                b = v1; bi = ii;
            } else {
                b2 = fmaxf(b2, v1);
            }
        }
        cnf[r] = s;
        if (b - b2 < GAP_T) {
            int idx = atomicAdd((int*)(smem + OFF_FLAGN), 1);
            ((int*)(smem + OFF_FLAGL))[idx] = r;
        } else if (has_ids) {
            out[NROWS*DDIM + (rbase + r)] = (float)bi;
        }
    }
    __syncthreads();

    // ---- write emb = bacc / sum ----
    {
        const int row_b = rowA + 8;
        const float inva = 1.0f / cnf[rowA];
        const float invb = 1.0f / cnf[row_b];
        float* oa = out + (size_t)(rbase + rowA)*DDIM;
        float* ob = out + (size_t)(rbase + row_b)*DDIM;
#pragma unroll
        for (int nt = 0; nt < 4; nt++) {
            int col = wc*32 + nt*8 + (lane & 3)*2;
            *(float2*)(oa + col) = make_float2(bacc[nt][0]*inva, bacc[nt][1]*inva);
            *(float2*)(ob + col) = make_float2(bacc[nt][2]*invb, bacc[nt][3]*invb);
        }
    }

    // ---- exact fp32 argmax fix-up for ambiguous rows (one warp per row) ----
    {
        const int nf = *(volatile int*)(smem + OFF_FLAGN);
        const int* fl = (const int*)(smem + OFF_FLAGL);
        for (int f = wid; f < nf; f += 16) {
            const int r = fl[f];
            const float* xr = x + (size_t)(rbase + r)*DDIM;
            float best = -CUDART_INF_F;
            int bi = 0;
            for (int k = lane; k < KCODES; k += 32) {
                const float* cr = cbg + (size_t)k*DDIM;
                float dot = 0.f, nrm = 0.f;
#pragma unroll
                for (int i = 0; i < 16; i++) {
                    float4 cv = ((const float4*)cr)[i];
                    float4 xv = ((const float4*)xr)[i];
                    dot = fmaf(xv.x, cv.x, dot); nrm = fmaf(cv.x, cv.x, nrm);
                    dot = fmaf(xv.y, cv.y, dot); nrm = fmaf(cv.y, cv.y, nrm);
                    dot = fmaf(xv.z, cv.z, dot); nrm = fmaf(cv.z, cv.z, nrm);
                    dot = fmaf(xv.w, cv.w, dot); nrm = fmaf(cv.w, cv.w, nrm);
                }
                float sv = fmaf(2.0f, dot, -nrm);
                if (sv > best) { best = sv; bi = k; }
            }
#pragma unroll
            for (int off = 16; off; off >>= 1) {
                float ob = __shfl_down_sync(0xffffffffu, best, off);
                int  obi = __shfl_down_sync(0xffffffffu, bi, off);
                if (ob > best || (ob == best && obi < bi)) { best = ob; bi = obi; }
            }
            if (lane == 0 && has_ids)
                out[NROWS*DDIM + (rbase + r)] = (float)bi;
        }
    }
}

extern "C" void kernel_launch(void* const* d_in, const int* in_sizes, int n_in,
                              void* d_out, int out_size) {
    const float* x  = (const float*)d_in[0];
    const float* cb = (const float*)d_in[1];
    const float* t  = (const float*)d_in[2];
    float* out = (float*)d_out;

    cudaFuncSetAttribute(fused_quantize,
                         cudaFuncAttributeMaxDynamicSharedMemorySize, SMEM_TOTAL);
    fused_quantize<<<NROWS/128, NTHR, SMEM_TOTAL>>>(x, cb, t, out, out_size);
}

// round 12
// speedup vs baseline: 1.6131x; 1.1723x over previous
#include <cuda_runtime.h>
#include <cuda_bf16.h>
#include <math_constants.h>
#include <cstdint>

#define NROWS   131072
#define DDIM    64
#define KCODES  1024
#define KC      64           // codes per chunk
#define NCHUNK  16
#define NTHR    256
#define RT      64           // rows per block tile
#define TSTRB   144          // universal bf16 tile row stride (bytes): 128+16, 16B-aligned, conflict-free
#define GAP_T   4e-3f

// ---- smem byte layout (all tiles 64 rows x 64 cols bf16, stride 144) ----
#define OFF_XH    0          // 9216
#define OFF_XL    9216
#define OFF_CTH   18432      // Ct: [dim][code]
#define OFF_CTL   27648
#define OFF_CH    36864      // C:  [code][dim]
#define OFF_CL    46080
#define OFF_EH    55296      // E:  [row][k]   (reused as reduction scratch)
#define OFF_EL    64512
#define OFF_CN    73728      // 64*4 norms / row sums
#define OFF_FLAGN 73984
#define OFF_FLAGL 73988      // up to 64 ints
#define SMEM_TOTAL 74368

__device__ __forceinline__ uint32_t smem_u32(const void* p) {
    uint32_t a;
    asm("{ .reg .u64 t; cvta.to.shared.u64 t, %1; cvt.u32.u64 %0, t; }" : "=r"(a) : "l"(p));
    return a;
}

#define LDSM_X4(r0,r1,r2,r3, addr) \
    asm volatile("ldmatrix.sync.aligned.m8n8.x4.shared.b16 {%0,%1,%2,%3}, [%4];" \
                 : "=r"(r0),"=r"(r1),"=r"(r2),"=r"(r3) : "r"(addr))
#define LDSM_X2T(r0,r1, addr) \
    asm volatile("ldmatrix.sync.aligned.m8n8.x2.trans.shared.b16 {%0,%1}, [%2];" \
                 : "=r"(r0),"=r"(r1) : "r"(addr))
#define MMA16816(d, a0,a1,a2,a3, b0,b1) \
    asm volatile("mma.sync.aligned.m16n8k16.row.col.f32.bf16.bf16.f32 " \
                 "{%0,%1,%2,%3}, {%4,%5,%6,%7}, {%8,%9}, {%0,%1,%2,%3};" \
                 : "+f"(d[0]),"+f"(d[1]),"+f"(d[2]),"+f"(d[3]) \
                 : "r"(a0),"r"(a1),"r"(a2),"r"(a3), "r"(b0),"r"(b1))

__device__ __forceinline__ unsigned rotl32(unsigned x, int r) {
    return __funnelshift_l(x, x, r);
}

// threefry2x32, key (0,42) — jax partitionable path: bits[j] = o0^o1, counter (0,j)
__device__ __forceinline__ unsigned threefry_xor_0_42(unsigned c1) {
    const unsigned ks0 = 0u, ks1 = 42u;
    const unsigned ks2 = 0x1BD11BDAu ^ ks0 ^ ks1;
    unsigned x0 = 0u + ks0;
    unsigned x1 = c1 + ks1;
#define TFR(r) { x0 += x1; x1 = rotl32(x1, r); x1 ^= x0; }
    TFR(13) TFR(15) TFR(26) TFR(6)
    x0 += ks1; x1 += ks2 + 1u;
    TFR(17) TFR(29) TFR(16) TFR(24)
    x0 += ks2; x1 += ks0 + 2u;
    TFR(13) TFR(15) TFR(26) TFR(6)
    x0 += ks0; x1 += ks1 + 3u;
    TFR(17) TFR(29) TFR(16) TFR(24)
    x0 += ks1; x1 += ks2 + 4u;
    TFR(13) TFR(15) TFR(26) TFR(6)
    x0 += ks2; x1 += ks0 + 5u;
#undef TFR
    return x0 ^ x1;
}

__device__ __forceinline__ float gumbel_from_bits(unsigned bits) {
    float u = (float)(bits >> 9) * 1.1920928955078125e-7f;
    u = fmaxf(u, 1.17549435e-38f);
    float v = (u < 0.5f) ? (-__logf(u)) : (-log1pf(u - 1.0f));
    return -__logf(v);
}

__device__ __forceinline__ void split_bf16(float v, unsigned short& h, unsigned short& l) {
    __nv_bfloat16 hb = __float2bfloat16(v);
    h = __bfloat16_as_ushort(hb);
    l = __bfloat16_as_ushort(__float2bfloat16(v - __bfloat162float(hb)));
}

__global__ __launch_bounds__(NTHR, 3)
void fused_quantize(const float* __restrict__ x,
                    const float* __restrict__ cbg,
                    const float* __restrict__ temp,
                    float* __restrict__ out,
                    int out_size)
{
    extern __shared__ char smem[];
    const uint32_t sb = smem_u32(smem);
    float* cnf = (float*)(smem + OFF_CN);

    const int tid  = threadIdx.x;
    const int wid  = tid >> 5;         // 0..7
    const int lane = tid & 31;
    const int wr   = wid & 3;          // row group (16 rows)
    const int wc   = wid >> 2;         // col half (32)
    const int rbase = blockIdx.x * RT;
    const float invT = 1.0f / temp[0];
    const bool has_ids = (out_size >= NROWS*DDIM + NROWS);

    if (tid == 0) *(int*)(smem + OFF_FLAGN) = 0;

    // ldmatrix lane addressing (A operands for both phases; all tiles stride TSTRB)
    const int a_row = wr*16 + (lane & 7) + ((lane >> 3) & 1)*8;
    const int a_col = ((lane >> 4) & 1) * 16;
    const uint32_t aoff = (uint32_t)(a_row*TSTRB + a_col);
    const int b_row = lane & 15;
    const int rowA  = wr*16 + (lane >> 2);

    // ---- build X bf16 hi/lo tiles [row][dim] (once; coalesced) ----
#pragma unroll
    for (int i = 0; i < 4; i++) {
        int q = tid + i*NTHR;          // 1024 float4s
        int row = q >> 4;
        int d4  = (q & 15) * 4;
        float4 v = *(const float4*)(x + (size_t)(rbase + row)*DDIM + d4);
        unsigned short h0,h1,h2,h3,l0,l1,l2,l3;
        split_bf16(v.x,h0,l0); split_bf16(v.y,h1,l1);
        split_bf16(v.z,h2,l2); split_bf16(v.w,h3,l3);
        uint32_t base = (uint32_t)(row*TSTRB + d4*2);
        *(uint2*)(smem + OFF_XH + base) =
            make_uint2((uint32_t)h0 | ((uint32_t)h1<<16), (uint32_t)h2 | ((uint32_t)h3<<16));
        *(uint2*)(smem + OFF_XL + base) =
            make_uint2((uint32_t)l0 | ((uint32_t)l1<<16), (uint32_t)l2 | ((uint32_t)l3<<16));
    }

    // persistent per-lane state: 2 rows (rowA, rowA+8)
    float sum2[2] = {0.f, 0.f};
    float pb1[2] = {-CUDART_INF_F, -CUDART_INF_F};
    float pb2[2] = {-CUDART_INF_F, -CUDART_INF_F};
    int   pi1[2] = {0, 0};
    float bacc[4][4];
#pragma unroll
    for (int nt = 0; nt < 4; nt++)
#pragma unroll
        for (int q = 0; q < 4; q++) bacc[nt][q] = 0.f;

    for (int c = 0; c < NCHUNK; c++) {
        const int kb = c * KC;
        __syncthreads();   // prev chunk's C/Ct/E consumed

        // ---- build C [code][dim] and Ct [dim][code] bf16 hi/lo tiles ----
        {
            const int code = tid & 63;
            const int dg   = tid >> 6;     // 16-dim group (0..3)
            const float* src = cbg + (size_t)(kb + code)*DDIM + dg*16;
            unsigned short hs[16], ls[16];
#pragma unroll
            for (int i = 0; i < 4; i++) {
                float4 v = ((const float4*)src)[i];
                split_bf16(v.x, hs[i*4+0], ls[i*4+0]);
                split_bf16(v.y, hs[i*4+1], ls[i*4+1]);
                split_bf16(v.z, hs[i*4+2], ls[i*4+2]);
                split_bf16(v.w, hs[i*4+3], ls[i*4+3]);
            }
            uint32_t hp[8], lp[8];
#pragma unroll
            for (int i = 0; i < 8; i++) {
                hp[i] = (uint32_t)hs[2*i] | ((uint32_t)hs[2*i+1] << 16);
                lp[i] = (uint32_t)ls[2*i] | ((uint32_t)ls[2*i+1] << 16);
            }
            uint32_t cbase = (uint32_t)(code*TSTRB + dg*32);
            *(uint4*)(smem + OFF_CH + cbase)      = make_uint4(hp[0],hp[1],hp[2],hp[3]);
            *(uint4*)(smem + OFF_CH + cbase + 16) = make_uint4(hp[4],hp[5],hp[6],hp[7]);
            *(uint4*)(smem + OFF_CL + cbase)      = make_uint4(lp[0],lp[1],lp[2],lp[3]);
            *(uint4*)(smem + OFF_CL + cbase + 16) = make_uint4(lp[4],lp[5],lp[6],lp[7]);
#pragma unroll
            for (int t = 0; t < 16; t++) {
                int d = dg*16 + t;
                *(unsigned short*)(smem + OFF_CTH + d*TSTRB + code*2) = hs[t];
                *(unsigned short*)(smem + OFF_CTL + d*TSTRB + code*2) = ls[t];
            }
        }
        // ---- exact fp32 code norms from gmem ----
        if (tid < KC) {
            const float* src = cbg + (size_t)(kb + tid)*DDIM;
            float s = 0.f;
#pragma unroll
            for (int i = 0; i < 16; i++) {
                float4 v = ((const float4*)src)[i];
                s = fmaf(v.x, v.x, s); s = fmaf(v.y, v.y, s);
                s = fmaf(v.z, v.z, s); s = fmaf(v.w, v.w, s);
            }
            cnf[tid] = s;
        }
        __syncthreads();

        // ========== Phase A (tensor): S = X(64x64) * Ct(64x64), 3-split ==========
        float sacc[4][4];
#pragma unroll
        for (int nt = 0; nt < 4; nt++)
#pragma unroll
            for (int q = 0; q < 4; q++) sacc[nt][q] = 0.f;

#pragma unroll
        for (int ks = 0; ks < 4; ks++) {
            const int k0b = ks * 32;          // 16 dims * 2 bytes
            uint32_t ah0,ah1,ah2,ah3, al0,al1,al2,al3;
            LDSM_X4(ah0,ah1,ah2,ah3, sb + OFF_XH + aoff + k0b);
            LDSM_X4(al0,al1,al2,al3, sb + OFF_XL + aoff + k0b);
            uint32_t browoff = (uint32_t)((ks*16 + b_row) * TSTRB);
#pragma unroll
            for (int nt = 0; nt < 4; nt++) {
                uint32_t n2 = (uint32_t)((wc*32 + nt*8) * 2);
                uint32_t bh0, bh1, bl0, bl1;
                LDSM_X2T(bh0, bh1, sb + OFF_CTH + browoff + n2);
                LDSM_X2T(bl0, bl1, sb + OFF_CTL + browoff + n2);
                MMA16816(sacc[nt], ah0,ah1,ah2,ah3, bh0,bh1);
                MMA16816(sacc[nt], ah0,ah1,ah2,ah3, bl0,bl1);
                MMA16816(sacc[nt], al0,al1,al2,al3, bh0,bh1);
            }
        }

        // hoist code norms for this lane's 8 codes
        float2 cnv[4];
#pragma unroll
        for (int nt = 0; nt < 4; nt++)
            cnv[nt] = *(float2*)(smem + OFF_CN + (wc*32 + nt*8 + (lane&3)*2)*4);

        // ---- epilogue on fragments: top2, gumbel, exp, E-tile write ----
#pragma unroll
        for (int slot = 0; slot < 2; slot++) {
            const int row = rowA + slot*8;
            const unsigned fb = (unsigned)(rbase + row)*1024u + (unsigned)kb;
            const uint32_t ebase = (uint32_t)(row*TSTRB + wc*64 + (lane&3)*4);
#pragma unroll
            for (int nt = 0; nt < 4; nt++) {
                const int c0 = wc*32 + nt*8 + (lane&3)*2;
                float s0 = fmaf(2.0f, sacc[nt][slot*2+0], -cnv[nt].x);
                float s1 = fmaf(2.0f, sacc[nt][slot*2+1], -cnv[nt].y);
                if (s0 > pb1[slot]) { pb2[slot] = pb1[slot]; pb1[slot] = s0; pi1[slot] = kb + c0; }
                else if (s0 > pb2[slot]) pb2[slot] = s0;
                if (s1 > pb1[slot]) { pb2[slot] = pb1[slot]; pb1[slot] = s1; pi1[slot] = kb + c0 + 1; }
                else if (s1 > pb2[slot]) pb2[slot] = s1;
                unsigned bt0 = threefry_xor_0_42(fb + (unsigned)c0);
                unsigned bt1 = threefry_xor_0_42(fb + (unsigned)c0 + 1u);
                float e0 = __expf((s0 + gumbel_from_bits(bt0)) * invT);
                float e1 = __expf((s1 + gumbel_from_bits(bt1)) * invT);
                sum2[slot] += e0 + e1;
                unsigned short h0,h1,l0,l1;
                split_bf16(e0,h0,l0); split_bf16(e1,h1,l1);
                *(uint32_t*)(smem + OFF_EH + ebase + nt*16) = (uint32_t)h0 | ((uint32_t)h1<<16);
                *(uint32_t*)(smem + OFF_EL + ebase + nt*16) = (uint32_t)l0 | ((uint32_t)l1<<16);
            }
        }
        __syncthreads();   // E visible

        // ========== Phase B (tensor): emb_raw += E(64x64) * C(64x64) ==========
#pragma unroll
        for (int ks = 0; ks < 4; ks++) {
            const int k0 = ks * 16;
            uint32_t ah0,ah1,ah2,ah3, al0,al1,al2,al3;
            LDSM_X4(ah0,ah1,ah2,ah3, sb + OFF_EH + aoff + k0*2);
            LDSM_X4(al0,al1,al2,al3, sb + OFF_EL + aoff + k0*2);
            uint32_t browoff = (uint32_t)((k0 + b_row) * TSTRB);
#pragma unroll
            for (int nt = 0; nt < 4; nt++) {
                uint32_t n2 = (uint32_t)((wc*32 + nt*8) * 2);
                uint32_t bh0, bh1, bl0, bl1;
                LDSM_X2T(bh0, bh1, sb + OFF_CH + browoff + n2);
                LDSM_X2T(bl0, bl1, sb + OFF_CL + browoff + n2);
                MMA16816(bacc[nt], ah0,ah1,ah2,ah3, bh0,bh1);
                MMA16816(bacc[nt], ah0,ah1,ah2,ah3, bl0,bl1);
                MMA16816(bacc[nt], al0,al1,al2,al3, bh0,bh1);
            }
        }
    }
    __syncthreads();   // all tiles consumed; EH reusable as scratch

    // ---- per-row reduction: 8 partials (4 quad-lanes x 2 wc) ----
    float* rsum = (float*)(smem + OFF_EH);   // [8][64]
    float* rb1  = rsum + 8*64;
    float* rb2  = rb1  + 8*64;
    int*   ri1  = (int*)(rb2 + 8*64);
    const int p = wc*4 + (lane & 3);
#pragma unroll
    for (int slot = 0; slot < 2; slot++) {
        int row = rowA + slot*8;
        rsum[p*64 + row] = sum2[slot];
        rb1 [p*64 + row] = pb1[slot];
        rb2 [p*64 + row] = pb2[slot];
        ri1 [p*64 + row] = pi1[slot];
    }
    __syncthreads();
    if (tid < RT) {
        const int r = tid;
        float s = 0.f, b = -CUDART_INF_F, b2 = -CUDART_INF_F;
        int bi = 0;
#pragma unroll
        for (int t = 0; t < 8; t++) {
            s += rsum[t*64 + r];
            float v1 = rb1[t*64 + r];
            float v2 = rb2[t*64 + r];
            int   ii = ri1[t*64 + r];
            if (v1 > b || (v1 == b && ii < bi)) {
                b2 = fmaxf(b, v2);
                b = v1; bi = ii;
            } else {
                b2 = fmaxf(b2, v1);
            }
        }
        cnf[r] = s;
        if (b - b2 < GAP_T) {
            int idx = atomicAdd((int*)(smem + OFF_FLAGN), 1);
            ((int*)(smem + OFF_FLAGL))[idx] = r;
        } else if (has_ids) {
            out[NROWS*DDIM + (rbase + r)] = (float)bi;
        }
    }
    __syncthreads();

    // ---- write emb = bacc / sum ----
    {
        const int row_b = rowA + 8;
        const float inva = 1.0f / cnf[rowA];
        const float invb = 1.0f / cnf[row_b];
        float* oa = out + (size_t)(rbase + rowA)*DDIM;
        float* ob = out + (size_t)(rbase + row_b)*DDIM;
#pragma unroll
        for (int nt = 0; nt < 4; nt++) {
            int col = wc*32 + nt*8 + (lane & 3)*2;
            *(float2*)(oa + col) = make_float2(bacc[nt][0]*inva, bacc[nt][1]*inva);
            *(float2*)(ob + col) = make_float2(bacc[nt][2]*invb, bacc[nt][3]*invb);
        }
    }

    // ---- exact fp32 argmax fix-up for ambiguous rows (one warp per row) ----
    {
        const int nf = *(volatile int*)(smem + OFF_FLAGN);
        const int* fl = (const int*)(smem + OFF_FLAGL);
        for (int f = wid; f < nf; f += 8) {
            const int r = fl[f];
            const float* xr = x + (size_t)(rbase + r)*DDIM;
            float best = -CUDART_INF_F;
            int bi = 0;
            for (int k = lane; k < KCODES; k += 32) {
                const float* cr = cbg + (size_t)k*DDIM;
                float dot = 0.f, nrm = 0.f;
#pragma unroll
                for (int i = 0; i < 16; i++) {
                    float4 cv = ((const float4*)cr)[i];
                    float4 xv = ((const float4*)xr)[i];
                    dot = fmaf(xv.x, cv.x, dot); nrm = fmaf(cv.x, cv.x, nrm);
                    dot = fmaf(xv.y, cv.y, dot); nrm = fmaf(cv.y, cv.y, nrm);
                    dot = fmaf(xv.z, cv.z, dot); nrm = fmaf(cv.z, cv.z, nrm);
                    dot = fmaf(xv.w, cv.w, dot); nrm = fmaf(cv.w, cv.w, nrm);
                }
                float sv = fmaf(2.0f, dot, -nrm);
                if (sv > best) { best = sv; bi = k; }
            }
#pragma unroll
            for (int off = 16; off; off >>= 1) {
                float ob = __shfl_down_sync(0xffffffffu, best, off);
                int  obi = __shfl_down_sync(0xffffffffu, bi, off);
                if (ob > best || (ob == best && obi < bi)) { best = ob; bi = obi; }
            }
            if (lane == 0 && has_ids)
                out[NROWS*DDIM + (rbase + r)] = (float)bi;
        }
    }
}

extern "C" void kernel_launch(void* const* d_in, const int* in_sizes, int n_in,
                              void* d_out, int out_size) {
    const float* x  = (const float*)d_in[0];
    const float* cb = (const float*)d_in[1];
    const float* t  = (const float*)d_in[2];
    float* out = (float*)d_out;

    cudaFuncSetAttribute(fused_quantize,
                         cudaFuncAttributeMaxDynamicSharedMemorySize, SMEM_TOTAL);
    fused_quantize<<<NROWS/RT, NTHR, SMEM_TOTAL>>>(x, cb, t, out, out_size);
}

// round 13
// speedup vs baseline: 1.8136x; 1.1243x over previous
#include <cuda_runtime.h>
#include <cuda_bf16.h>
#include <math_constants.h>
#include <cstdint>

#define NROWS   131072
#define DDIM    64
#define KCODES  1024
#define KC      64           // codes per chunk
#define NCHUNK  16
#define NTHR    256
#define RT      64           // rows per block tile
#define TSTRB   144          // bf16 tile row stride (bytes)
#define GAP_T   4e-3f

// ---- smem byte layout (tiles 64x64 bf16, stride 144) ----
#define OFF_XH    0          // 9216
#define OFF_XL    9216
#define OFF_CH    18432      // C: [code][dim]  (shared by phase A + B)
#define OFF_CL    27648
#define OFF_EH    36864      // E: [row][k]  (reused as reduction scratch)
#define OFF_EL    46080
#define OFF_CN    55296      // 64*4 norms / row sums
#define OFF_FLAGN 55552
#define OFF_FLAGL 55556      // up to 64 ints
#define SMEM_TOTAL 56064

__device__ __forceinline__ uint32_t smem_u32(const void* p) {
    uint32_t a;
    asm("{ .reg .u64 t; cvta.to.shared.u64 t, %1; cvt.u32.u64 %0, t; }" : "=r"(a) : "l"(p));
    return a;
}

#define LDSM_X4(r0,r1,r2,r3, addr) \
    asm volatile("ldmatrix.sync.aligned.m8n8.x4.shared.b16 {%0,%1,%2,%3}, [%4];" \
                 : "=r"(r0),"=r"(r1),"=r"(r2),"=r"(r3) : "r"(addr))
#define LDSM_X2(r0,r1, addr) \
    asm volatile("ldmatrix.sync.aligned.m8n8.x2.shared.b16 {%0,%1}, [%2];" \
                 : "=r"(r0),"=r"(r1) : "r"(addr))
#define LDSM_X2T(r0,r1, addr) \
    asm volatile("ldmatrix.sync.aligned.m8n8.x2.trans.shared.b16 {%0,%1}, [%2];" \
                 : "=r"(r0),"=r"(r1) : "r"(addr))
#define MMA16816(d, a0,a1,a2,a3, b0,b1) \
    asm volatile("mma.sync.aligned.m16n8k16.row.col.f32.bf16.bf16.f32 " \
                 "{%0,%1,%2,%3}, {%4,%5,%6,%7}, {%8,%9}, {%0,%1,%2,%3};" \
                 : "+f"(d[0]),"+f"(d[1]),"+f"(d[2]),"+f"(d[3]) \
                 : "r"(a0),"r"(a1),"r"(a2),"r"(a3), "r"(b0),"r"(b1))

__device__ __forceinline__ unsigned rotl32(unsigned x, int r) {
    return __funnelshift_l(x, x, r);
}

// threefry2x32, key (0,42) — jax partitionable path: bits[j] = o0^o1, counter (0,j)
__device__ __forceinline__ unsigned threefry_xor_0_42(unsigned c1) {
    const unsigned ks0 = 0u, ks1 = 42u;
    const unsigned ks2 = 0x1BD11BDAu ^ ks0 ^ ks1;
    unsigned x0 = 0u + ks0;
    unsigned x1 = c1 + ks1;
#define TFR(r) { x0 += x1; x1 = rotl32(x1, r); x1 ^= x0; }
    TFR(13) TFR(15) TFR(26) TFR(6)
    x0 += ks1; x1 += ks2 + 1u;
    TFR(17) TFR(29) TFR(16) TFR(24)
    x0 += ks2; x1 += ks0 + 2u;
    TFR(13) TFR(15) TFR(26) TFR(6)
    x0 += ks0; x1 += ks1 + 3u;
    TFR(17) TFR(29) TFR(16) TFR(24)
    x0 += ks1; x1 += ks2 + 4u;
    TFR(13) TFR(15) TFR(26) TFR(6)
    x0 += ks2; x1 += ks0 + 5u;
#undef TFR
    return x0 ^ x1;
}

// u from bits; inner -log(u): fast __logf (abs err 2^-21.4 on [0.5,2]) except the
// winning tail u>=0.99 where log1pf keeps g accurate. Returns v = -log(u) > 0.
__device__ __forceinline__ float neglog_u(unsigned bits) {
    float u = (float)(bits >> 9) * 1.1920928955078125e-7f;
    u = fmaxf(u, 1.17549435e-38f);
    float v;
    if (u < 0.99f) v = -__logf(u);
    else           v = -log1pf(u - 1.0f);     // rare branch (~1% of lanes)
    return v;
}

__device__ __forceinline__ void split_bf16(float v, unsigned short& h, unsigned short& l) {
    __nv_bfloat16 hb = __float2bfloat16(v);
    h = __bfloat16_as_ushort(hb);
    l = __bfloat16_as_ushort(__float2bfloat16(v - __bfloat162float(hb)));
}

__global__ __launch_bounds__(NTHR, 4)
void fused_quantize(const float* __restrict__ x,
                    const float* __restrict__ cbg,
                    const float* __restrict__ temp,
                    float* __restrict__ out,
                    int out_size)
{
    extern __shared__ char smem[];
    const uint32_t sb = smem_u32(smem);
    float* cnf = (float*)(smem + OFF_CN);

    const int tid  = threadIdx.x;
    const int wid  = tid >> 5;         // 0..7
    const int lane = tid & 31;
    const int wr   = wid & 3;          // row group (16 rows)
    const int wc   = wid >> 2;         // col half (32)
    const int rbase = blockIdx.x * RT;
    const float invT = 1.0f / temp[0];
    const float c1   = invT * 1.4426950408889634f;   // invT*log2(e)
    const bool has_ids = (out_size >= NROWS*DDIM + NROWS);

    if (tid == 0) *(int*)(smem + OFF_FLAGN) = 0;

    // ldmatrix lane addressing
    const int a_row = wr*16 + (lane & 7) + ((lane >> 3) & 1)*8;
    const int a_col = ((lane >> 4) & 1) * 16;
    const uint32_t aoff = (uint32_t)(a_row*TSTRB + a_col);
    // phase-A B operand: NON-trans x2 on C[code][dim]; lanes 0-15 supply rows
    //   lane i<8 -> C[nblk+i][kblk], lane 8+i -> C[nblk+i][kblk+8]
    const uint32_t bAoff = (uint32_t)((lane & 7)*TSTRB + ((lane >> 3) & 1)*16);
    const int b_row = lane & 15;       // phase-B trans rows (k=code)
    const int rowA  = wr*16 + (lane >> 2);

    // ---- build X bf16 hi/lo tiles [row][dim] (once; coalesced) ----
#pragma unroll
    for (int i = 0; i < 4; i++) {
        int q = tid + i*NTHR;          // 1024 float4s
        int row = q >> 4;
        int d4  = (q & 15) * 4;
        float4 v = *(const float4*)(x + (size_t)(rbase + row)*DDIM + d4);
        unsigned short h0,h1,h2,h3,l0,l1,l2,l3;
        split_bf16(v.x,h0,l0); split_bf16(v.y,h1,l1);
        split_bf16(v.z,h2,l2); split_bf16(v.w,h3,l3);
        uint32_t base = (uint32_t)(row*TSTRB + d4*2);
        *(uint2*)(smem + OFF_XH + base) =
            make_uint2((uint32_t)h0 | ((uint32_t)h1<<16), (uint32_t)h2 | ((uint32_t)h3<<16));
        *(uint2*)(smem + OFF_XL + base) =
            make_uint2((uint32_t)l0 | ((uint32_t)l1<<16), (uint32_t)l2 | ((uint32_t)l3<<16));
    }

    // persistent per-lane state: 2 rows (rowA, rowA+8)
    float sum2[2] = {0.f, 0.f};
    float pb1[2] = {-CUDART_INF_F, -CUDART_INF_F};
    float pb2[2] = {-CUDART_INF_F, -CUDART_INF_F};
    int   pi1[2] = {0, 0};
    float bacc[4][4];
#pragma unroll
    for (int nt = 0; nt < 4; nt++)
#pragma unroll
        for (int q = 0; q < 4; q++) bacc[nt][q] = 0.f;

    for (int c = 0; c < NCHUNK; c++) {
        const int kb = c * KC;
        __syncthreads();   // prev chunk's C/E consumed

        // ---- build C [code][dim] bf16 hi/lo tile ----
        {
            const int code = tid & 63;
            const int dg   = tid >> 6;     // 16-dim group (0..3)
            const float* src = cbg + (size_t)(kb + code)*DDIM + dg*16;
            unsigned short hs[16], ls[16];
#pragma unroll
            for (int i = 0; i < 4; i++) {
                float4 v = ((const float4*)src)[i];
                split_bf16(v.x, hs[i*4+0], ls[i*4+0]);
                split_bf16(v.y, hs[i*4+1], ls[i*4+1]);
                split_bf16(v.z, hs[i*4+2], ls[i*4+2]);
                split_bf16(v.w, hs[i*4+3], ls[i*4+3]);
            }
            uint32_t hp[8], lp[8];
#pragma unroll
            for (int i = 0; i < 8; i++) {
                hp[i] = (uint32_t)hs[2*i] | ((uint32_t)hs[2*i+1] << 16);
                lp[i] = (uint32_t)ls[2*i] | ((uint32_t)ls[2*i+1] << 16);
            }
            uint32_t cbase = (uint32_t)(code*TSTRB + dg*32);
            *(uint4*)(smem + OFF_CH + cbase)      = make_uint4(hp[0],hp[1],hp[2],hp[3]);
            *(uint4*)(smem + OFF_CH + cbase + 16) = make_uint4(hp[4],hp[5],hp[6],hp[7]);
            *(uint4*)(smem + OFF_CL + cbase)      = make_uint4(lp[0],lp[1],lp[2],lp[3]);
            *(uint4*)(smem + OFF_CL + cbase + 16) = make_uint4(lp[4],lp[5],lp[6],lp[7]);
        }
        // ---- exact fp32 code norms from gmem ----
        if (tid < KC) {
            const float* src = cbg + (size_t)(kb + tid)*DDIM;
            float s = 0.f;
#pragma unroll
            for (int i = 0; i < 16; i++) {
                float4 v = ((const float4*)src)[i];
                s = fmaf(v.x, v.x, s); s = fmaf(v.y, v.y, s);
                s = fmaf(v.z, v.z, s); s = fmaf(v.w, v.w, s);
            }
            cnf[tid] = s;
        }
        __syncthreads();

        // ========== Phase A (tensor): S = X(64x64) * C^T(64x64), 3-split ==========
        float sacc[4][4];
#pragma unroll
        for (int nt = 0; nt < 4; nt++)
#pragma unroll
            for (int q = 0; q < 4; q++) sacc[nt][q] = 0.f;

#pragma unroll
        for (int ks = 0; ks < 4; ks++) {
            const int k0b = ks * 32;          // 16 dims * 2 bytes
            uint32_t ah0,ah1,ah2,ah3, al0,al1,al2,al3;
            LDSM_X4(ah0,ah1,ah2,ah3, sb + OFF_XH + aoff + k0b);
            LDSM_X4(al0,al1,al2,al3, sb + OFF_XL + aoff + k0b);
#pragma unroll
            for (int nt = 0; nt < 4; nt++) {
                // B tile rows = codes (n), non-trans; k = dims
                uint32_t boff = bAoff + (uint32_t)((wc*32 + nt*8)*TSTRB) + (uint32_t)k0b;
                uint32_t bh0, bh1, bl0, bl1;
                LDSM_X2(bh0, bh1, sb + OFF_CH + boff);
                LDSM_X2(bl0, bl1, sb + OFF_CL + boff);
                MMA16816(sacc[nt], ah0,ah1,ah2,ah3, bh0,bh1);
                MMA16816(sacc[nt], ah0,ah1,ah2,ah3, bl0,bl1);
                MMA16816(sacc[nt], al0,al1,al2,al3, bh0,bh1);
            }
        }

        // ---- epilogue on fragments: top2, gumbel, exp2, E-tile write ----
#pragma unroll
        for (int slot = 0; slot < 2; slot++) {
            const int row = rowA + slot*8;
            const unsigned fb = (unsigned)(rbase + row)*1024u + (unsigned)kb;
            const uint32_t ebase = (uint32_t)(row*TSTRB + wc*64 + (lane&3)*4);
#pragma unroll
            for (int nt = 0; nt < 4; nt++) {
                const int c0 = wc*32 + nt*8 + (lane&3)*2;
                float2 cnv = *(float2*)(smem + OFF_CN + c0*4);
                float s0 = fmaf(2.0f, sacc[nt][slot*2+0], -cnv.x);
                float s1 = fmaf(2.0f, sacc[nt][slot*2+1], -cnv.y);
                if (s0 > pb1[slot]) { pb2[slot] = pb1[slot]; pb1[slot] = s0; pi1[slot] = kb + c0; }
                else if (s0 > pb2[slot]) pb2[slot] = s0;
                if (s1 > pb1[slot]) { pb2[slot] = pb1[slot]; pb1[slot] = s1; pi1[slot] = kb + c0 + 1; }
                else if (s1 > pb2[slot]) pb2[slot] = s1;
                float v0 = neglog_u(threefry_xor_0_42(fb + (unsigned)c0));
                float v1 = neglog_u(threefry_xor_0_42(fb + (unsigned)c0 + 1u));
                // e = exp((s + -log v)/T) = exp2(s*c1 - log2(v)*invT)
                float e0 = exp2f(fmaf(__log2f(v0), -invT, s0*c1));
                float e1 = exp2f(fmaf(__log2f(v1), -invT, s1*c1));
                sum2[slot] += e0 + e1;
                unsigned short h0,h1,l0,l1;
                split_bf16(e0,h0,l0); split_bf16(e1,h1,l1);
                *(uint32_t*)(smem + OFF_EH + ebase + nt*16) = (uint32_t)h0 | ((uint32_t)h1<<16);
                *(uint32_t*)(smem + OFF_EL + ebase + nt*16) = (uint32_t)l0 | ((uint32_t)l1<<16);
            }
        }
        __syncthreads();   // E visible

        // ========== Phase B (tensor): emb_raw += E(64x64) * C(64x64) ==========
#pragma unroll
        for (int ks = 0; ks < 4; ks++) {
            const int k0 = ks * 16;
            uint32_t ah0,ah1,ah2,ah3, al0,al1,al2,al3;
            LDSM_X4(ah0,ah1,ah2,ah3, sb + OFF_EH + aoff + k0*2);
            LDSM_X4(al0,al1,al2,al3, sb + OFF_EL + aoff + k0*2);
            uint32_t browoff = (uint32_t)((k0 + b_row) * TSTRB);
#pragma unroll
            for (int nt = 0; nt < 4; nt++) {
                uint32_t n2 = (uint32_t)((wc*32 + nt*8) * 2);
                uint32_t bh0, bh1, bl0, bl1;
                LDSM_X2T(bh0, bh1, sb + OFF_CH + browoff + n2);
                LDSM_X2T(bl0, bl1, sb + OFF_CL + browoff + n2);
                MMA16816(bacc[nt], ah0,ah1,ah2,ah3, bh0,bh1);
                MMA16816(bacc[nt], ah0,ah1,ah2,ah3, bl0,bl1);
                MMA16816(bacc[nt], al0,al1,al2,al3, bh0,bh1);
            }
        }
    }
    __syncthreads();   // all tiles consumed; EH reusable as scratch

    // ---- per-row reduction: 8 partials (4 quad-lanes x 2 wc) ----
    float* rsum = (float*)(smem + OFF_EH);   // [8][64]
    float* rb1  = rsum + 8*64;
    float* rb2  = rb1  + 8*64;
    int*   ri1  = (int*)(rb2 + 8*64);
    const int p = wc*4 + (lane & 3);
#pragma unroll
    for (int slot = 0; slot < 2; slot++) {
        int row = rowA + slot*8;
        rsum[p*64 + row] = sum2[slot];
        rb1 [p*64 + row] = pb1[slot];
        rb2 [p*64 + row] = pb2[slot];
        ri1 [p*64 + row] = pi1[slot];
    }
    __syncthreads();
    if (tid < RT) {
        const int r = tid;
        float s = 0.f, b = -CUDART_INF_F, b2 = -CUDART_INF_F;
        int bi = 0;
#pragma unroll
        for (int t = 0; t < 8; t++) {
            s += rsum[t*64 + r];
            float v1 = rb1[t*64 + r];
            float v2 = rb2[t*64 + r];
            int   ii = ri1[t*64 + r];
            if (v1 > b || (v1 == b && ii < bi)) {
                b2 = fmaxf(b, v2);
                b = v1; bi = ii;
            } else {
                b2 = fmaxf(b2, v1);
            }
        }
        cnf[r] = s;
        if (b - b2 < GAP_T) {
            int idx = atomicAdd((int*)(smem + OFF_FLAGN), 1);
            ((int*)(smem + OFF_FLAGL))[idx] = r;
        } else if (has_ids) {
            out[NROWS*DDIM + (rbase + r)] = (float)bi;
        }
    }
    __syncthreads();

    // ---- write emb = bacc / sum ----
    {
        const int row_b = rowA + 8;
        const float inva = 1.0f / cnf[rowA];
        const float invb = 1.0f / cnf[row_b];
        float* oa = out + (size_t)(rbase + rowA)*DDIM;
        float* ob = out + (size_t)(rbase + row_b)*DDIM;
#pragma unroll
        for (int nt = 0; nt < 4; nt++) {
            int col = wc*32 + nt*8 + (lane & 3)*2;
            *(float2*)(oa + col) = make_float2(bacc[nt][0]*inva, bacc[nt][1]*inva);
            *(float2*)(ob + col) = make_float2(bacc[nt][2]*invb, bacc[nt][3]*invb);
        }
    }

    // ---- exact fp32 argmax fix-up for ambiguous rows (one warp per row) ----
    {
        const int nf = *(volatile int*)(smem + OFF_FLAGN);
        const int* fl = (const int*)(smem + OFF_FLAGL);
        for (int f = wid; f < nf; f += 8) {
            const int r = fl[f];
            const float* xr = x + (size_t)(rbase + r)*DDIM;
            float best = -CUDART_INF_F;
            int bi = 0;
            for (int k = lane; k < KCODES; k += 32) {
                const float* cr = cbg + (size_t)k*DDIM;
                float dot = 0.f, nrm = 0.f;
#pragma unroll
                for (int i = 0; i < 16; i++) {
                    float4 cv = ((const float4*)cr)[i];
                    float4 xv = ((const float4*)xr)[i];
                    dot = fmaf(xv.x, cv.x, dot); nrm = fmaf(cv.x, cv.x, nrm);
                    dot = fmaf(xv.y, cv.y, dot); nrm = fmaf(cv.y, cv.y, nrm);
                    dot = fmaf(xv.z, cv.z, dot); nrm = fmaf(cv.z, cv.z, nrm);
                    dot = fmaf(xv.w, cv.w, dot); nrm = fmaf(cv.w, cv.w, nrm);
                }
                float sv = fmaf(2.0f, dot, -nrm);
                if (sv > best) { best = sv; bi = k; }
            }
#pragma unroll
            for (int off = 16; off; off >>= 1) {
                float ob = __shfl_down_sync(0xffffffffu, best, off);
                int  obi = __shfl_down_sync(0xffffffffu, bi, off);
                if (ob > best || (ob == best && obi < bi)) { best = ob; bi = obi; }
            }
            if (lane == 0 && has_ids)
                out[NROWS*DDIM + (rbase + r)] = (float)bi;
        }
    }
}

extern "C" void kernel_launch(void* const* d_in, const int* in_sizes, int n_in,
                              void* d_out, int out_size) {
    const float* x  = (const float*)d_in[0];
    const float* cb = (const float*)d_in[1];
    const float* t  = (const float*)d_in[2];
    float* out = (float*)d_out;

    cudaFuncSetAttribute(fused_quantize,
                         cudaFuncAttributeMaxDynamicSharedMemorySize, SMEM_TOTAL);
    fused_quantize<<<NROWS/RT, NTHR, SMEM_TOTAL>>>(x, cb, t, out, out_size);
}